// round 15
// baseline (speedup 1.0000x reference)
#include <cuda_runtime.h>
#include <math.h>

// Hausdorff, D=H=W=20, V=8000, batch 2. Exact integer squared-EDT.
// ONE kernel, 80 blocks: block = (transform t, z-plane z0).
// Front/body = best-measured R7/R14 path. Tail: warp leaders submit their
// warp-max DIRECTLY to the per-sample encoded global slot via red.release
// BEFORE the final sync (latency overlapped); post-sync = acq_rel arrival
// only; last block decodes 2 slots and resets (graph-replay safe).
// Encoding (monotone): 1..1083 -> sqrt/20 ; 2000 -> 999 ; 3000 -> 1e9 ; 0 none.

#define INF_S 32000   // max legit squared distance = 3*19^2 = 1083
#define PAD   8

__device__ unsigned g_slot[2 * PAD];   // per-sample encoded haus max; zero-init
__device__ unsigned g_done = 0;

__device__ __forceinline__ void red_max_release(unsigned* p, unsigned v)
{
    asm volatile("red.release.gpu.global.max.u32 [%0], %1;"
                 :: "l"(p), "r"(v) : "memory");
}

__device__ __forceinline__ unsigned atom_add_acq_rel(unsigned* p, unsigned v)
{
    unsigned old;
    asm volatile("atom.acq_rel.gpu.global.add.u32 %0, [%1], %2;"
                 : "=r"(old) : "l"(p), "r"(v) : "memory");
    return old;
}

__global__ void __launch_bounds__(416, 1)
haus_plane(const float* __restrict__ predict,
           const float* __restrict__ targetp,
           float* __restrict__ out)
{
    __shared__ int F1[400];
    __shared__ int F2[400];
    __shared__ int wany[13];           // per-warp "set has any point" flags

    const int b  = blockIdx.x;         // t*20 + z0
    const int t  = b / 20, z0 = b - t * 20;
    const int n  = t >> 1,  m  = t & 1;
    const float* setSrc = (m ? targetp : predict) + n * 8000;
    const float* othSrc = (m ? predict : targetp) + n * 8000;
    const int tid  = threadIdx.x;
    const int lane = tid & 31, warp = tid >> 5;

    int x = 0, y = 0, oo = 0;
    unsigned rowbits = 0;
    if (tid < 400) {
        x = tid / 20; y = tid - x * 20;
        // Own (x,y) row over z: 20 contiguous floats = 5 x float4 (MLP=5).
        const float4* rp = (const float4*)(setSrc + tid * 20);
        float ov = othSrc[tid * 20 + z0];          // other mask at own cell
        #pragma unroll
        for (int q = 0; q < 5; q++) {
            float4 v = rp[q];
            // jnp.round == round-half-even == rintf
            rowbits |= (rintf(v.x) != 0.0f ? 1u : 0u) << (q * 4 + 0);
            rowbits |= (rintf(v.y) != 0.0f ? 1u : 0u) << (q * 4 + 1);
            rowbits |= (rintf(v.z) != 0.0f ? 1u : 0u) << (q * 4 + 2);
            rowbits |= (rintf(v.w) != 0.0f ? 1u : 0u) << (q * 4 + 3);
        }
        // z-pass at fixed z0: nearest set bit in own row, O(1).
        int dist = 100;
        unsigned lo = rowbits & ((2u << z0) - 1u);
        if (lo) dist = z0 - (31 - __clz(lo));
        unsigned hi = rowbits >> z0;
        if (hi) dist = min(dist, __ffs(hi) - 1);
        F1[tid] = (dist <= 19) ? dist * dist : INF_S;

        int s = (rowbits >> z0) & 1;
        oo = (rintf(ov) != 0.0f) & (s ^ 1);        // "other-only" point
    }
    // per-warp set-nonempty flag (400 rows cover the whole volume)
    int anyW = __any_sync(0xffffffffu, rowbits != 0);
    if (lane == 0) wany[warp] = anyW;
    __syncthreads();                               // publishes F1 and wany

    // ---- y-pass: F2(x,y) = min_yp F1(x,yp) + (y-yp)^2 ----
    if (tid < 400) {
        int c[20];
        const int base = x * 20;
        #pragma unroll
        for (int yp = 0; yp < 20; yp++) {
            int dy = y - yp;
            c[yp] = F1[base + yp] + dy * dy;
        }
        #pragma unroll
        for (int st = 1; st < 20; st <<= 1)
            #pragma unroll
            for (int i = 0; i + st < 20; i += (st << 1)) c[i] = min(c[i], c[i + st]);
        F2[tid] = c[0];
    }
    __syncthreads();

    // ---- x-pass + classification ----
    int enc = 0;                                   // d2 of other-only point; 0 = none
    if (tid < 400) {
        int c[20];
        #pragma unroll
        for (int xp = 0; xp < 20; xp++) {
            int dx = x - xp;
            c[xp] = F2[xp * 20 + y] + dx * dx;
        }
        #pragma unroll
        for (int st = 1; st < 20; st <<= 1)
            #pragma unroll
            for (int i = 0; i + st < 20; i += (st << 1)) c[i] = min(c[i], c[i + st]);
        if (oo) enc = c[0];                        // >= 1 (cell not in set)
    }
    enc = __reduce_max_sync(0xffffffffu, enc);

    // ---- warp leaders submit to the global slot BEFORE the final sync ----
    if (lane == 0 && enc) {
        int blockAny = 0;
        #pragma unroll
        for (int w = 0; w < 13; w++) blockAny |= wany[w];   // stable since sync-1
        unsigned e = blockAny ? (unsigned)enc : (m ? 3000u : 2000u);
        red_max_release(&g_slot[n * PAD], e);
    }
    __syncthreads();                               // all submissions ordered pre-arrival

    // ---- arrival + finalize ----
    if (tid == 0) {
        unsigned done = atom_add_acq_rel(&g_done, 1);   // release chains the reds
        if (done == 79) {                               // acquire: sees all slots
            float sum = 0.0f;
            #pragma unroll
            for (int nn = 0; nn < 2; nn++) {
                unsigned ev = *(volatile unsigned*)&g_slot[nn * PAD];
                float h = 0.0f;
                if (ev) h = (ev >= 3000u) ? 1e9f
                          : (ev >= 2000u) ? 999.0f
                          : sqrtf((float)ev) * 0.05f;
                sum += h;
                *(volatile unsigned*)&g_slot[nn * PAD] = 0;
            }
            out[0] = sum * 0.5f;
            *(volatile unsigned*)&g_done = 0;           // restore static-init state
        }
    }
}

extern "C" void kernel_launch(void* const* d_in, const int* in_sizes, int n_in,
                              void* d_out, int out_size)
{
    const float* predict = (const float*)d_in[0];
    const float* targetp = (const float*)d_in[1];
    haus_plane<<<80, 416>>>(predict, targetp, (float*)d_out);
}

// round 16
// speedup vs baseline: 1.2694x; 1.2694x over previous
#include <cuda_runtime.h>
#include <math.h>

// Hausdorff, D=H=W=20, V=8000, batch 2. Exact integer squared-EDT.
// ONE kernel, 80 blocks: block = (transform t, z-plane z0). R14 structure
// (best measured: 7.14us): strided float4 row front, O(1) clz/ffs z-pass,
// tree-min y/x passes in SMEM, fence-free encoded tail. Tail micro-fix vs
// R14: warp maxima via plain smem stores + tid0 scan (no smem atomics).
// Encoding (monotone): 1..1083 -> sqrt/20 ; 2000 -> 999 ; 3000 -> 1e9 ; 0 none.

#define INF_S 32000   // max legit squared distance = 3*19^2 = 1083
#define PAD   8

__device__ unsigned g_slot[2 * PAD];   // per-sample encoded haus max; zero-init
__device__ unsigned g_done = 0;

__device__ __forceinline__ unsigned atom_add_acq_rel(unsigned* p, unsigned v)
{
    unsigned old;
    asm volatile("atom.acq_rel.gpu.global.add.u32 %0, [%1], %2;"
                 : "=r"(old) : "l"(p), "r"(v) : "memory");
    return old;
}

__global__ void __launch_bounds__(416, 1)
haus_plane(const float* __restrict__ predict,
           const float* __restrict__ targetp,
           float* __restrict__ out)
{
    __shared__ int F1[400];
    __shared__ int F2[400];
    __shared__ int wmax[13];           // per-warp enc maxima (plain stores)
    __shared__ int sany;

    const int b  = blockIdx.x;         // t*20 + z0
    const int t  = b / 20, z0 = b - t * 20;
    const int n  = t >> 1,  m  = t & 1;
    const float* setSrc = (m ? targetp : predict) + n * 8000;
    const float* othSrc = (m ? predict : targetp) + n * 8000;
    const int tid  = threadIdx.x;
    const int lane = tid & 31, warp = tid >> 5;

    if (tid == 0) sany = 0;

    int x = 0, y = 0, oo = 0;
    unsigned rowbits = 0;
    if (tid < 400) {
        x = tid / 20; y = tid - x * 20;
        // Own (x,y) row over z: 20 contiguous floats = 5 x float4 (MLP=5).
        const float4* rp = (const float4*)(setSrc + tid * 20);
        float ov = othSrc[tid * 20 + z0];          // other mask at own cell
        #pragma unroll
        for (int q = 0; q < 5; q++) {
            float4 v = rp[q];
            // jnp.round == round-half-even == rintf
            rowbits |= (rintf(v.x) != 0.0f ? 1u : 0u) << (q * 4 + 0);
            rowbits |= (rintf(v.y) != 0.0f ? 1u : 0u) << (q * 4 + 1);
            rowbits |= (rintf(v.z) != 0.0f ? 1u : 0u) << (q * 4 + 2);
            rowbits |= (rintf(v.w) != 0.0f ? 1u : 0u) << (q * 4 + 3);
        }
        // z-pass at fixed z0: nearest set bit in own row, O(1).
        int dist = 100;
        unsigned lo = rowbits & ((2u << z0) - 1u);
        if (lo) dist = z0 - (31 - __clz(lo));
        unsigned hi = rowbits >> z0;
        if (hi) dist = min(dist, __ffs(hi) - 1);
        F1[tid] = (dist <= 19) ? dist * dist : INF_S;

        int s = (rowbits >> z0) & 1;
        oo = (rintf(ov) != 0.0f) & (s ^ 1);        // "other-only" point
    }
    // anyS: any set bit anywhere (400 rows cover the whole volume)
    int anyW = __any_sync(0xffffffffu, rowbits != 0);
    if (lane == 0 && anyW) sany = 1;               // benign race
    __syncthreads();

    // ---- y-pass: F2(x,y) = min_yp F1(x,yp) + (y-yp)^2 ----
    if (tid < 400) {
        int c[20];
        const int base = x * 20;
        #pragma unroll
        for (int yp = 0; yp < 20; yp++) {
            int dy = y - yp;
            c[yp] = F1[base + yp] + dy * dy;
        }
        #pragma unroll
        for (int st = 1; st < 20; st <<= 1)
            #pragma unroll
            for (int i = 0; i + st < 20; i += (st << 1)) c[i] = min(c[i], c[i + st]);
        F2[tid] = c[0];
    }
    __syncthreads();

    // ---- x-pass + classification ----
    int enc = 0;                                   // d2 of other-only point; 0 = none
    if (tid < 400) {
        int c[20];
        #pragma unroll
        for (int xp = 0; xp < 20; xp++) {
            int dx = x - xp;
            c[xp] = F2[xp * 20 + y] + dx * dx;
        }
        #pragma unroll
        for (int st = 1; st < 20; st <<= 1)
            #pragma unroll
            for (int i = 0; i + st < 20; i += (st << 1)) c[i] = min(c[i], c[i + st]);
        if (oo) enc = c[0];                        // >= 1 (cell not in set)
    }
    enc = __reduce_max_sync(0xffffffffu, enc);
    if (lane == 0) wmax[warp] = enc;               // plain store, no atomics
    __syncthreads();

    // ---- tail: tid0 scans 13 warp maxima, ONE relaxed atomicMax + arrival ----
    if (tid == 0) {
        int red = 0;
        #pragma unroll
        for (int w = 0; w < 13; w++) red = max(red, wmax[w]);
        if (red) {
            // Encoding (monotone under decode): see header.
            unsigned e = sany ? (unsigned)red : (m ? 3000u : 2000u);
            atomicMax(&g_slot[n * PAD], e);
        }
        unsigned done = atom_add_acq_rel(&g_done, 1);   // release publishes the max
        if (done == 79) {                               // acquire: sees all slots
            float sum = 0.0f;
            #pragma unroll
            for (int nn = 0; nn < 2; nn++) {
                unsigned ev = *(volatile unsigned*)&g_slot[nn * PAD];
                float h = 0.0f;
                if (ev) h = (ev >= 3000u) ? 1e9f
                          : (ev >= 2000u) ? 999.0f
                          : sqrtf((float)ev) * 0.05f;
                sum += h;
                *(volatile unsigned*)&g_slot[nn * PAD] = 0;
            }
            out[0] = sum * 0.5f;
            *(volatile unsigned*)&g_done = 0;           // restore static-init state
        }
    }
}

extern "C" void kernel_launch(void* const* d_in, const int* in_sizes, int n_in,
                              void* d_out, int out_size)
{
    const float* predict = (const float*)d_in[0];
    const float* targetp = (const float*)d_in[1];
    haus_plane<<<80, 416>>>(predict, targetp, (float*)d_out);
}